// round 2
// baseline (speedup 1.0000x reference)
#include <cuda_runtime.h>
#include <math.h>

#define BN_NODES 81920
#define T_STEPS 16
#define FDIM 64
#define NE 327680
#define BATCH 4096
#define D1 1280
#define D2 640
#define D3 320

// ---------------- scratch (static device globals; no allocation) ----------------
__device__ float g_H[(size_t)BN_NODES * FDIM];          // hidden state
__device__ float g_Tx[(size_t)BN_NODES * 128];          // [Tx1 | Tx2] cols 0..63 / 64..127
__device__ float g_gx[(size_t)BN_NODES * 192];          // X-cheb outputs [xz|xr|xh]
__device__ float g_gh[(size_t)BN_NODES * 128];          // H-cheb outputs [hz|hr]
__device__ float g_ghh[(size_t)BN_NODES * FDIM];        // HR-cheb output [hh]
__device__ float g_Z[(size_t)BN_NODES * FDIM];          // update gate
__device__ float g_HR[(size_t)BN_NODES * FDIM];         // H * R
__device__ float g_deg[BN_NODES];
__device__ int   g_cnt[BN_NODES];
__device__ int   g_cur[BN_NODES];
__device__ int   g_rp[BN_NODES + 1];
__device__ int   g_csrc[NE];
__device__ float g_cw[NE];
__device__ float g_nw[NE];
__device__ float g_Wx[192 * 192];
__device__ float g_Wh[192 * 128];
__device__ float g_Whh[192 * 64];
__device__ float g_m1[(size_t)BATCH * D2];
__device__ float g_m2[(size_t)BATCH * D3];

// ---------------- prep kernels ----------------
__global__ void k_zero() {
    int i = blockIdx.x * blockDim.x + threadIdx.x;
    if (i < BN_NODES * FDIM) g_H[i] = 0.f;
    if (i < BN_NODES) { g_deg[i] = 0.f; g_cnt[i] = 0; g_cur[i] = 0; }
}

__global__ void k_deg(const int* __restrict__ ei, const float* __restrict__ ew) {
    int e = blockIdx.x * blockDim.x + threadIdx.x;
    if (e < NE) atomicAdd(&g_deg[ei[e]], ew[e]);
}

__global__ void k_nw(const int* __restrict__ ei, const float* __restrict__ ew) {
    int e = blockIdx.x * blockDim.x + threadIdx.x;
    if (e < NE) {
        int s = ei[e], d = ei[NE + e];
        float ds = g_deg[s], dd = g_deg[d];
        float is = ds > 0.f ? rsqrtf(ds) : 0.f;
        float id = dd > 0.f ? rsqrtf(dd) : 0.f;
        g_nw[e] = -is * ew[e] * id;
        atomicAdd(&g_cnt[d], 1);
    }
}

// single-block scan: row_ptr = exclusive scan of per-dst counts
__global__ void k_scan() {
    __shared__ int sh[1024];
    int tid = threadIdx.x;
    if (tid == 0) g_rp[0] = 0;
    int offset = 0;
    for (int base = 0; base < BN_NODES; base += 1024) {
        int v = g_cnt[base + tid];
        sh[tid] = v;
        __syncthreads();
        for (int d = 1; d < 1024; d <<= 1) {
            int t = (tid >= d) ? sh[tid - d] : 0;
            __syncthreads();
            sh[tid] += t;
            __syncthreads();
        }
        g_rp[base + tid + 1] = offset + sh[tid];
        int tot = sh[1023];
        __syncthreads();
        offset += tot;
    }
}

__global__ void k_scatter(const int* __restrict__ ei) {
    int e = blockIdx.x * blockDim.x + threadIdx.x;
    if (e < NE) {
        int d = ei[NE + e];
        int pos = g_rp[d] + atomicAdd(&g_cur[d], 1);
        g_csrc[pos] = ei[e];
        g_cw[pos] = g_nw[e];
    }
}

// pack Chebyshev weights into concatenated [192 x Cout] matrices
__global__ void k_packW(const float* __restrict__ Wxz, const float* __restrict__ Wxr,
                        const float* __restrict__ Wxh, const float* __restrict__ Whz,
                        const float* __restrict__ Whr, const float* __restrict__ Whh) {
    int i = blockIdx.x * blockDim.x + threadIdx.x;
    const int NX = 192 * 192, NH = 192 * 128, NHH = 192 * 64;
    if (i < NX) {
        int r = i / 192, c = i % 192;
        int kk = r >> 6, ii = r & 63, g = c >> 6, j = c & 63;
        const float* W = (g == 0) ? Wxz : ((g == 1) ? Wxr : Wxh);
        g_Wx[i] = W[kk * 4096 + ii * 64 + j];
    } else if (i < NX + NH) {
        int q = i - NX;
        int r = q / 128, c = q % 128;
        int kk = r >> 6, ii = r & 63, g = c >> 6, j = c & 63;
        const float* W = (g == 0) ? Whz : Whr;
        g_Wh[q] = W[kk * 4096 + ii * 64 + j];
    } else if (i < NX + NH + NHH) {
        int q = i - NX - NH;
        int r = q >> 6, c = q & 63;
        int kk = r >> 6, ii = r & 63;
        g_Whh[q] = Whh[kk * 4096 + ii * 64 + c];
    }
}

// ---------------- SpMM: out[n,:] = scale * sum_e w_e * in[src_e,:]  (- sub[n,:]) ----------------
__global__ void k_spmm(const float* __restrict__ in, int ldi,
                       float* __restrict__ out, int ldo,
                       const float* __restrict__ sub, int lds, float scale) {
    int node = blockIdx.x * 8 + (threadIdx.x >> 5);
    int lane = threadIdx.x & 31;
    if (node >= BN_NODES) return;
    int s = g_rp[node], e = g_rp[node + 1];
    float ax = 0.f, ay = 0.f;
    for (int i = s; i < e; i++) {
        int sr = g_csrc[i];
        float w = g_cw[i];
        float2 v = *(const float2*)(in + (size_t)sr * ldi + lane * 2);
        ax = fmaf(w, v.x, ax);
        ay = fmaf(w, v.y, ay);
    }
    ax *= scale; ay *= scale;
    if (sub) {
        float2 sv = *(const float2*)(sub + (size_t)node * lds + lane * 2);
        ax -= sv.x; ay -= sv.y;
    }
    *(float2*)(out + (size_t)node * ldo + lane * 2) = make_float2(ax, ay);
}

// ---------------- SGEMM: O[M,Cout] = [A0(:, 0:64) | A12(:, 0:128)] @ W  ----------------
// A split: k < 64 -> A0 (lda0), k >= 64 -> A12 (stride 128). If A12 == null, all K from A0.
// BM=128, BNt=64, BK=16, 256 threads, per-thread 8x4.
template <int RELU>
__global__ void k_gemm(const float* __restrict__ A0, int lda0,
                       const float* __restrict__ A12,
                       const float* __restrict__ W, int ldw,
                       const float* __restrict__ bias,
                       float* __restrict__ O, int ldo, int Kdim) {
    __shared__ float As[16][128];
    __shared__ float Bs[16][64];
    int tid = threadIdx.x;
    int tx = tid & 15, ty = tid >> 4;
    int m0 = blockIdx.x * 128;
    int j0 = blockIdx.y * 64;
    float acc[8][4] = {};

    for (int kt = 0; kt < Kdim; kt += 16) {
        const float* Ap;
        int lda;
        if (A12 != nullptr && kt >= 64) { Ap = A12 + (kt - 64); lda = 128; }
        else { Ap = A0 + kt; lda = lda0; }
#pragma unroll
        for (int l = 0; l < 2; l++) {
            int idx = tid + l * 256;          // 0..511
            int m = idx >> 2;                 // 0..127
            int kc = (idx & 3) * 4;           // 0,4,8,12
            float4 v = *(const float4*)(Ap + (size_t)(m0 + m) * lda + kc);
            As[kc + 0][m] = v.x; As[kc + 1][m] = v.y;
            As[kc + 2][m] = v.z; As[kc + 3][m] = v.w;
        }
        {
            int k = tid >> 4;                 // 0..15
            int jc = (tid & 15) * 4;          // 0..60
            *(float4*)&Bs[k][jc] = *(const float4*)(W + (size_t)(kt + k) * ldw + j0 + jc);
        }
        __syncthreads();
#pragma unroll
        for (int kk = 0; kk < 16; kk++) {
            float4 a0 = *(float4*)&As[kk][ty * 8];
            float4 a1 = *(float4*)&As[kk][ty * 8 + 4];
            float4 b = *(float4*)&Bs[kk][tx * 4];
            float av[8] = {a0.x, a0.y, a0.z, a0.w, a1.x, a1.y, a1.z, a1.w};
            float bv[4] = {b.x, b.y, b.z, b.w};
#pragma unroll
            for (int i = 0; i < 8; i++)
#pragma unroll
                for (int j = 0; j < 4; j++)
                    acc[i][j] = fmaf(av[i], bv[j], acc[i][j]);
        }
        __syncthreads();
    }

    float4 bb = make_float4(0.f, 0.f, 0.f, 0.f);
    if (bias) bb = *(const float4*)(bias + j0 + tx * 4);
#pragma unroll
    for (int i = 0; i < 8; i++) {
        float4 o;
        o.x = acc[i][0] + bb.x;
        o.y = acc[i][1] + bb.y;
        o.z = acc[i][2] + bb.z;
        o.w = acc[i][3] + bb.w;
        if (RELU) {
            o.x = fmaxf(o.x, 0.f); o.y = fmaxf(o.y, 0.f);
            o.z = fmaxf(o.z, 0.f); o.w = fmaxf(o.w, 0.f);
        }
        *(float4*)(O + (size_t)(m0 + ty * 8 + i) * ldo + j0 + tx * 4) = o;
    }
}

// ---------------- elementwise GRU kernels ----------------
__global__ void k_gates(const float* __restrict__ bxz, const float* __restrict__ bhz,
                        const float* __restrict__ bxr, const float* __restrict__ bhr) {
    int i = blockIdx.x * blockDim.x + threadIdx.x;
    if (i >= BN_NODES * FDIM) return;
    int n = i >> 6, f = i & 63;
    float z = g_gx[(size_t)n * 192 + f] + g_gh[(size_t)n * 128 + f] + bxz[f] + bhz[f];
    z = 1.f / (1.f + expf(-z));
    float r = g_gx[(size_t)n * 192 + 64 + f] + g_gh[(size_t)n * 128 + 64 + f] + bxr[f] + bhr[f];
    r = 1.f / (1.f + expf(-r));
    g_Z[i] = z;
    g_HR[i] = g_H[i] * r;
}

__global__ void k_update(const float* __restrict__ bxh, const float* __restrict__ bhh) {
    int i = blockIdx.x * blockDim.x + threadIdx.x;
    if (i >= BN_NODES * FDIM) return;
    int n = i >> 6, f = i & 63;
    float ht = tanhf(g_gx[(size_t)n * 192 + 128 + f] + bxh[f] + g_ghh[i] + bhh[f]);
    float z = g_Z[i];
    float h = z * g_H[i] + (1.f - z) * ht;
    g_H[i] = fmaxf(h, 0.f);
}

// ---------------- final tiny GEMM + softmax (warp per row) ----------------
__global__ void k_final(const float* __restrict__ W3, const float* __restrict__ b3,
                        float* __restrict__ out) {
    int row = blockIdx.x * 8 + (threadIdx.x >> 5);
    int lane = threadIdx.x & 31;
    if (row >= BATCH) return;
    float s0 = 0.f, s1 = 0.f;
    for (int k = lane; k < D3; k += 32) {
        float a = g_m2[(size_t)row * D3 + k];
        s0 = fmaf(a, W3[k * 2 + 0], s0);
        s1 = fmaf(a, W3[k * 2 + 1], s1);
    }
#pragma unroll
    for (int o = 16; o; o >>= 1) {
        s0 += __shfl_down_sync(0xffffffffu, s0, o);
        s1 += __shfl_down_sync(0xffffffffu, s1, o);
    }
    if (lane == 0) {
        float l0 = s0 + b3[0], l1 = s1 + b3[1];
        float m = fmaxf(l0, l1);
        float e0 = expf(l0 - m), e1 = expf(l1 - m);
        float inv = 1.f / (e0 + e1);
        out[row * 2 + 0] = e0 * inv;
        out[row * 2 + 1] = e1 * inv;
    }
}

// ---------------- host launcher ----------------
extern "C" void kernel_launch(void* const* d_in, const int* in_sizes, int n_in,
                              void* d_out, int out_size) {
    const float* x = (const float*)d_in[0];
    const int* ei = (const int*)d_in[1];
    const float* ew = (const float*)d_in[2];
    const float* Wxz = (const float*)d_in[3];  const float* bxz = (const float*)d_in[4];
    const float* Whz = (const float*)d_in[5];  const float* bhz = (const float*)d_in[6];
    const float* Wxr = (const float*)d_in[7];  const float* bxr = (const float*)d_in[8];
    const float* Whr = (const float*)d_in[9];  const float* bhr = (const float*)d_in[10];
    const float* Wxh = (const float*)d_in[11]; const float* bxh = (const float*)d_in[12];
    const float* Whh = (const float*)d_in[13]; const float* bhh = (const float*)d_in[14];
    const float* W1 = (const float*)d_in[15];  const float* b1 = (const float*)d_in[16];
    const float* W2 = (const float*)d_in[17];  const float* b2 = (const float*)d_in[18];
    const float* W3 = (const float*)d_in[19];  const float* b3 = (const float*)d_in[20];
    float* out = (float*)d_out;

    float *p_H, *p_Tx, *p_gx, *p_gh, *p_ghh, *p_HR, *p_Wx, *p_Wh, *p_Whh, *p_m1, *p_m2;
    cudaGetSymbolAddress((void**)&p_H, g_H);
    cudaGetSymbolAddress((void**)&p_Tx, g_Tx);
    cudaGetSymbolAddress((void**)&p_gx, g_gx);
    cudaGetSymbolAddress((void**)&p_gh, g_gh);
    cudaGetSymbolAddress((void**)&p_ghh, g_ghh);
    cudaGetSymbolAddress((void**)&p_HR, g_HR);
    cudaGetSymbolAddress((void**)&p_Wx, g_Wx);
    cudaGetSymbolAddress((void**)&p_Wh, g_Wh);
    cudaGetSymbolAddress((void**)&p_Whh, g_Whh);
    cudaGetSymbolAddress((void**)&p_m1, g_m1);
    cudaGetSymbolAddress((void**)&p_m2, g_m2);

    const int EW_THREADS = 256;
    const int EW_GRID = (BN_NODES * FDIM + EW_THREADS - 1) / EW_THREADS;
    const int EDGE_GRID = (NE + 255) / 256;
    const int SPMM_GRID = BN_NODES / 8;

    // graph preprocessing (every launch; deterministic work)
    k_zero<<<EW_GRID, EW_THREADS>>>();
    k_deg<<<EDGE_GRID, 256>>>(ei, ew);
    k_nw<<<EDGE_GRID, 256>>>(ei, ew);
    k_scan<<<1, 1024>>>();
    k_scatter<<<EDGE_GRID, 256>>>(ei);
    k_packW<<<(192 * (192 + 128 + 64) + 255) / 256, 256>>>(Wxz, Wxr, Wxh, Whz, Whr, Whh);

    for (int t = 0; t < T_STEPS; t++) {
        const float* xt = x + (size_t)t * BN_NODES * FDIM;

        // X basis: Tx1 = L X ; Tx2 = 2 L Tx1 - X ; gx = [X|Tx1|Tx2] @ Wx
        k_spmm<<<SPMM_GRID, 256>>>(xt, FDIM, p_Tx, 128, nullptr, 0, 1.f);
        k_spmm<<<SPMM_GRID, 256>>>(p_Tx, 128, p_Tx + 64, 128, xt, FDIM, 2.f);
        k_gemm<0><<<dim3(640, 3), 256>>>(xt, FDIM, p_Tx, p_Wx, 192, nullptr, p_gx, 192, 192);

        // H basis
        k_spmm<<<SPMM_GRID, 256>>>(p_H, FDIM, p_Tx, 128, nullptr, 0, 1.f);
        k_spmm<<<SPMM_GRID, 256>>>(p_Tx, 128, p_Tx + 64, 128, p_H, FDIM, 2.f);
        k_gemm<0><<<dim3(640, 2), 256>>>(p_H, FDIM, p_Tx, p_Wh, 128, nullptr, p_gh, 128, 192);

        // gates: Z, R, HR
        k_gates<<<EW_GRID, EW_THREADS>>>(bxz, bhz, bxr, bhr);

        // HR basis
        k_spmm<<<SPMM_GRID, 256>>>(p_HR, FDIM, p_Tx, 128, nullptr, 0, 1.f);
        k_spmm<<<SPMM_GRID, 256>>>(p_Tx, 128, p_Tx + 64, 128, p_HR, FDIM, 2.f);
        k_gemm<0><<<dim3(640, 1), 256>>>(p_HR, FDIM, p_Tx, p_Whh, 64, nullptr, p_ghh, 64, 192);

        // GRU update
        k_update<<<EW_GRID, EW_THREADS>>>(bxh, bhh);
    }

    // MLP head on H viewed as [4096, 1280]
    k_gemm<1><<<dim3(BATCH / 128, D2 / 64), 256>>>(p_H, D1, nullptr, W1, D2, b1, p_m1, D2, D1);
    k_gemm<1><<<dim3(BATCH / 128, D3 / 64), 256>>>(p_m1, D2, nullptr, W2, D3, b2, p_m2, D3, D2);
    k_final<<<BATCH / 8, 256>>>(W3, b3, out);
}